// round 14
// baseline (speedup 1.0000x reference)
#include <cuda_runtime.h>
#include <cuda_fp16.h>
#include <cstdint>

// ============================================================================
// BitLinear: y = (clip(LN(x) * 128/gamma, +-(128-.01)) @ w) * beta*gamma/128
//   x: [4,2048,4096] f32 -> M=8192, K=4096;  w: [4096,4096] f32 (+-1)
// Base sm_100 target (no tcgen05). mma.sync HMMA + ldmatrix + cp.async.
// R14: GEMM = R6 exact config (best measured: 790 us, at the ~13.3 cyc/HMMA
// issue ceiling established over 8 structural variants). Optimization moves
// to prep: LN rows now 128 thr/row with MLP=8 (was 256 thr/row, MLP=4) to
// saturate HBM; 2 rows per 256-thr block via named barriers.
// ============================================================================

constexpr int M_TOT = 8192;
constexpr int N_TOT = 4096;
constexpr int K_TOT = 4096;

__device__ __half g_A[(size_t)M_TOT * K_TOT];   // 64 MB
__device__ __half g_Bt[(size_t)N_TOT * K_TOT];  // 32 MB

// ---------------------------------------------------------------------------
__device__ __forceinline__ uint32_t smem_u32(const void* p) {
    uint32_t a;
    asm("{ .reg .u64 t; cvta.to.shared.u64 t, %1; cvt.u32.u64 %0, t; }"
        : "=r"(a) : "l"(p));
    return a;
}

#define CP_ASYNC16(smem, gptr) \
    asm volatile("cp.async.cg.shared.global [%0], [%1], 16;" \
                 :: "r"(smem), "l"(gptr) : "memory")
#define CP_COMMIT() asm volatile("cp.async.commit_group;" ::: "memory")
#define CP_WAIT(n)  asm volatile("cp.async.wait_group %0;" :: "n"(n) : "memory")

#define LDSM_X4(r0, r1, r2, r3, addr) \
    asm volatile("ldmatrix.sync.aligned.m8n8.x4.shared.b16 {%0,%1,%2,%3}, [%4];" \
                 : "=r"(r0), "=r"(r1), "=r"(r2), "=r"(r3) : "r"(addr))

#define MMA16816(c0, c1, c2, c3, a0, a1, a2, a3, b0, b1) \
    asm volatile("mma.sync.aligned.m16n8k16.row.col.f32.f16.f16.f32 " \
                 "{%0,%1,%2,%3}, {%4,%5,%6,%7}, {%8,%9}, {%0,%1,%2,%3};" \
                 : "+f"(c0), "+f"(c1), "+f"(c2), "+f"(c3) \
                 : "r"(a0), "r"(a1), "r"(a2), "r"(a3), "r"(b0), "r"(b1))

// ---------------------------------------------------------------------------
// Kernel 1 (merged): blocks [0, 4096) = LN+quant (2 rows/block, 128 thr/row,
// named barriers); blocks [4096, 20480) = wconv 32x32 transpose.
// ---------------------------------------------------------------------------
__global__ void __launch_bounds__(256) prep_kernel(
    const float* __restrict__ x, const float* __restrict__ w,
    const float* __restrict__ lng, const float* __restrict__ lnb,
    const float* __restrict__ bet, const float* __restrict__ gam)
{
    int tid = threadIdx.x;
    if (blockIdx.x < 4096) {
        int g = tid >> 7;                  // group 0/1 (warps 0-3 / 4-7)
        int t = tid & 127;
        int row = blockIdx.x * 2 + g;
        const float4* xr = reinterpret_cast<const float4*>(x + (size_t)row * K_TOT);

        // MLP=8: eight independent 16B loads in flight per thread
        float4 v[8];
        float s = 0.f, s2 = 0.f;
#pragma unroll
        for (int i = 0; i < 8; i++) {
            v[i] = xr[t + i * 128];
            s  += v[i].x + v[i].y + v[i].z + v[i].w;
            s2 += v[i].x * v[i].x + v[i].y * v[i].y + v[i].z * v[i].z + v[i].w * v[i].w;
        }
#pragma unroll
        for (int o = 16; o; o >>= 1) {
            s  += __shfl_xor_sync(0xffffffffu, s, o);
            s2 += __shfl_xor_sync(0xffffffffu, s2, o);
        }
        __shared__ float rs[2][4], rs2[2][4];
        if ((t & 31) == 0) { rs[g][t >> 5] = s; rs2[g][t >> 5] = s2; }
        asm volatile("bar.sync %0, 128;" :: "r"(g) : "memory");
        s  = rs[g][0]  + rs[g][1]  + rs[g][2]  + rs[g][3];
        s2 = rs2[g][0] + rs2[g][1] + rs2[g][2] + rs2[g][3];

        const float inv_k = 1.0f / (float)K_TOT;
        float mu   = s * inv_k;
        float var  = s2 * inv_k - mu * mu;
        float rstd = rsqrtf(var + 1e-5f);
        float gm = *gam;
        float qs = 128.0f / gm;
        float os = (*bet) * gm * (1.0f / 128.0f);
        const float lo = -128.0f + 0.01f;
        const float hi =  128.0f - 0.01f;

        const float4* lg4 = reinterpret_cast<const float4*>(lng);
        const float4* lb4 = reinterpret_cast<const float4*>(lnb);
        uint2* dst = reinterpret_cast<uint2*>(g_A + (size_t)row * K_TOT);

#pragma unroll
        for (int i = 0; i < 8; i++) {
            int idx = t + i * 128;
            float4 gv = lg4[idx], bv = lb4[idx];
            float e0 = ((v[i].x - mu) * rstd * gv.x + bv.x) * qs;
            float e1 = ((v[i].y - mu) * rstd * gv.y + bv.y) * qs;
            float e2 = ((v[i].z - mu) * rstd * gv.z + bv.z) * qs;
            float e3 = ((v[i].w - mu) * rstd * gv.w + bv.w) * qs;
            e0 = fminf(fmaxf(e0, lo), hi) * os;
            e1 = fminf(fmaxf(e1, lo), hi) * os;
            e2 = fminf(fmaxf(e2, lo), hi) * os;
            e3 = fminf(fmaxf(e3, lo), hi) * os;
            __half2 h0 = __floats2half2_rn(e0, e1);
            __half2 h1 = __floats2half2_rn(e2, e3);
            uint2 u;
            u.x = *reinterpret_cast<uint32_t*>(&h0);
            u.y = *reinterpret_cast<uint32_t*>(&h1);
            dst[idx] = u;
        }
    } else {
        __shared__ float t2[32][33];
        int b2 = blockIdx.x - 4096;
        int k0 = (b2 & 127) * 32, n0 = (b2 >> 7) * 32;
        int tx = tid & 31, ty = tid >> 5;
#pragma unroll
        for (int j = 0; j < 32; j += 8)
            t2[ty + j][tx] = w[(size_t)(k0 + ty + j) * N_TOT + n0 + tx];
        __syncthreads();
#pragma unroll
        for (int pass = 0; pass < 2; pass++) {
            int idx = tid + pass * 256;
            int n  = idx >> 4;
            int kp = idx & 15;
            __half2 h = __floats2half2_rn(t2[2 * kp][n], t2[2 * kp + 1][n]);
            *reinterpret_cast<__half2*>(&g_Bt[(size_t)(n0 + n) * K_TOT + k0 + 2 * kp]) = h;
        }
    }
}

// ---------------------------------------------------------------------------
// Kernel 2: HMMA GEMM  out[M,N] = A[M,K] @ Bt[N,K]^T   (R6 exact config)
//   CTA 128x256, BK=64, 4 stages, 512 threads / 16 warps (4m x 4n) of 32x64,
//   double-buffered fragments. Best measured: 790.1 us @ tensor 64.4%.
// ---------------------------------------------------------------------------
constexpr int BM = 128, BN = 256, BK = 64, STAGES = 4;
constexpr int KT = K_TOT / BK;                     // 64
constexpr int ROW_B = 144;                         // padded row bytes
constexpr int A_STAGE = BM * ROW_B;                // 18432
constexpr int B_STAGE = BN * ROW_B;                // 36864
constexpr int STAGE_B = A_STAGE + B_STAGE;         // 55296
constexpr int SMEM_GEMM = STAGES * STAGE_B;        // 221184
constexpr int NT = 512;

__global__ void __launch_bounds__(NT, 1) gemm_kernel(float* __restrict__ out)
{
    extern __shared__ char smem[];
    uint32_t sb = smem_u32(smem);
    int tid = threadIdx.x;
    int wid = tid >> 5;
    int lid = tid & 31;
    int n0 = blockIdx.x * BN;
    int m0 = blockIdx.y * BM;

    int wm = wid & 3;              // m offset wm*32
    int wn = wid >> 2;             // n offset wn*64

    const __half* gA = g_A + (size_t)m0 * K_TOT;
    const __half* gB = g_Bt + (size_t)n0 * K_TOT;

    uint32_t a_off = (uint32_t)(wm * 32 + (lid & 15)) * ROW_B + (uint32_t)(lid >> 4) * 16;
    uint32_t b_off = (uint32_t)(wn * 64 + (lid & 7) + ((lid & 16) ? 8 : 0)) * ROW_B
                   + (uint32_t)((lid & 8) ? 16 : 0);

    float acc[2][8][4];
#pragma unroll
    for (int i = 0; i < 2; i++)
#pragma unroll
        for (int j = 0; j < 8; j++)
#pragma unroll
            for (int q = 0; q < 4; q++) acc[i][j][q] = 0.f;

#define LOAD_STAGE(stg, kofs)                                                        \
    do {                                                                             \
        uint32_t _st = sb + (uint32_t)(stg) * STAGE_B;                               \
        _Pragma("unroll")                                                            \
        for (int r = 0; r < 2; r++) {                                                \
            int idx = tid + r * NT;                                                  \
            CP_ASYNC16(_st + (uint32_t)(idx >> 3) * ROW_B + (uint32_t)(idx & 7) * 16,\
                       gA + (size_t)(idx >> 3) * K_TOT + (kofs) + (idx & 7) * 8);    \
        }                                                                            \
        _Pragma("unroll")                                                            \
        for (int r = 0; r < 4; r++) {                                                \
            int idx = tid + r * NT;                                                  \
            CP_ASYNC16(_st + A_STAGE + (uint32_t)(idx >> 3) * ROW_B                  \
                           + (uint32_t)(idx & 7) * 16,                               \
                       gB + (size_t)(idx >> 3) * K_TOT + (kofs) + (idx & 7) * 8);    \
        }                                                                            \
        CP_COMMIT();                                                                 \
    } while (0)

#define LOAD_FRAGS(buf, sa, sB, kh)                                                  \
    do {                                                                             \
        _Pragma("unroll")                                                            \
        for (int mt = 0; mt < 2; mt++)                                               \
            LDSM_X4(af[buf][mt][0], af[buf][mt][1], af[buf][mt][2], af[buf][mt][3],  \
                    (sa) + (uint32_t)mt * (16 * ROW_B) + (uint32_t)(kh) * 32);       \
        _Pragma("unroll")                                                            \
        for (int nb = 0; nb < 4; nb++)                                               \
            LDSM_X4(bf[buf][nb][0], bf[buf][nb][1], bf[buf][nb][2], bf[buf][nb][3],  \
                    (sB) + (uint32_t)nb * (16 * ROW_B) + (uint32_t)(kh) * 32);       \
    } while (0)

    // prologue: fill stages 0..2
#pragma unroll
    for (int s = 0; s < STAGES - 1; s++) LOAD_STAGE(s, s * BK);

    int s_load = STAGES - 1;

    for (int kt = 0; kt < KT; kt++) {
        CP_WAIT(2);
        __syncthreads();

        if (kt + STAGES - 1 < KT) {
            LOAD_STAGE(s_load, (kt + STAGES - 1) * BK);
        } else {
            CP_COMMIT();   // keep group ledger aligned with CP_WAIT(2)
        }
        if (++s_load == STAGES) s_load = 0;

        uint32_t sa = sb + (uint32_t)(kt & 3) * STAGE_B + a_off;
        uint32_t sB = sb + (uint32_t)(kt & 3) * STAGE_B + A_STAGE + b_off;

        uint32_t af[2][2][4], bf[2][4][4];
        LOAD_FRAGS(0, sa, sB, 0);
#pragma unroll
        for (int kh = 0; kh < 4; kh++) {
            int cur = kh & 1;
            if (kh < 3) LOAD_FRAGS(cur ^ 1, sa, sB, kh + 1);
#pragma unroll
            for (int mt = 0; mt < 2; mt++) {
#pragma unroll
                for (int nb = 0; nb < 4; nb++) {
                    MMA16816(acc[mt][2 * nb][0], acc[mt][2 * nb][1],
                             acc[mt][2 * nb][2], acc[mt][2 * nb][3],
                             af[cur][mt][0], af[cur][mt][1], af[cur][mt][2], af[cur][mt][3],
                             bf[cur][nb][0], bf[cur][nb][1]);
                    MMA16816(acc[mt][2 * nb + 1][0], acc[mt][2 * nb + 1][1],
                             acc[mt][2 * nb + 1][2], acc[mt][2 * nb + 1][3],
                             af[cur][mt][0], af[cur][mt][1], af[cur][mt][2], af[cur][mt][3],
                             bf[cur][nb][2], bf[cur][nb][3]);
                }
            }
        }
    }

    // epilogue: direct v2 stores
    int r_base = m0 + wm * 32 + (lid >> 2);
    int c_base = n0 + wn * 64 + 2 * (lid & 3);
#pragma unroll
    for (int mt = 0; mt < 2; mt++) {
#pragma unroll
        for (int nt = 0; nt < 8; nt++) {
            int r = r_base + mt * 16;
            int c = c_base + nt * 8;
            float* p0 = out + (size_t)r * N_TOT + c;
            float* p1 = out + (size_t)(r + 8) * N_TOT + c;
            p0[0] = acc[mt][nt][0]; p0[1] = acc[mt][nt][1];
            p1[0] = acc[mt][nt][2]; p1[1] = acc[mt][nt][3];
        }
    }
}

// ---------------------------------------------------------------------------
extern "C" void kernel_launch(void* const* d_in, const int* in_sizes, int n_in,
                              void* d_out, int out_size)
{
    const float* x     = (const float*)d_in[0];
    const float* w     = (const float*)d_in[1];
    const float* lng   = (const float*)d_in[2];
    const float* lnb   = (const float*)d_in[3];
    const float* beta  = (const float*)d_in[4];
    const float* gamma = (const float*)d_in[5];
    float* out = (float*)d_out;

    prep_kernel<<<4096 + 16384, 256>>>(x, w, lng, lnb, beta, gamma);

    cudaFuncSetAttribute(gemm_kernel,
                         cudaFuncAttributeMaxDynamicSharedMemorySize, SMEM_GEMM);
    gemm_kernel<<<dim3(N_TOT / BN, M_TOT / BM), NT, SMEM_GEMM>>>(out);
}

// round 15
// speedup vs baseline: 1.1384x; 1.1384x over previous
#include <cuda_runtime.h>
#include <cuda_fp16.h>
#include <cstdint>

// ============================================================================
// BitLinear: y = (clip(LN(x) * 128/gamma, +-(128-.01)) @ w) * beta*gamma/128
//   x: [4,2048,4096] f32 -> M=8192, K=4096;  w: [4096,4096] f32 (+-1)
// Base sm_100 target (no tcgen05). mma.sync HMMA + ldmatrix + cp.async.
// R15 = round-6 kernel byte-for-byte (best measured total: 835.6 us).
// 512 thr / 16 warps (4/SMSP), warp tile 32x64, CTA 128x256, BK=64,
// 4 stages, double-buffered fragments + cross-kt prefetch, CP_WAIT(1).
// ============================================================================

constexpr int M_TOT = 8192;
constexpr int N_TOT = 4096;
constexpr int K_TOT = 4096;

__device__ __half g_A[(size_t)M_TOT * K_TOT];   // 64 MB
__device__ __half g_Bt[(size_t)N_TOT * K_TOT];  // 32 MB

// ---------------------------------------------------------------------------
__device__ __forceinline__ uint32_t smem_u32(const void* p) {
    uint32_t a;
    asm("{ .reg .u64 t; cvta.to.shared.u64 t, %1; cvt.u32.u64 %0, t; }"
        : "=r"(a) : "l"(p));
    return a;
}

#define CP_ASYNC16(smem, gptr) \
    asm volatile("cp.async.cg.shared.global [%0], [%1], 16;" \
                 :: "r"(smem), "l"(gptr) : "memory")
#define CP_COMMIT() asm volatile("cp.async.commit_group;" ::: "memory")
#define CP_WAIT(n)  asm volatile("cp.async.wait_group %0;" :: "n"(n) : "memory")

#define LDSM_X4(r0, r1, r2, r3, addr) \
    asm volatile("ldmatrix.sync.aligned.m8n8.x4.shared.b16 {%0,%1,%2,%3}, [%4];" \
                 : "=r"(r0), "=r"(r1), "=r"(r2), "=r"(r3) : "r"(addr))

#define MMA16816(c0, c1, c2, c3, a0, a1, a2, a3, b0, b1) \
    asm volatile("mma.sync.aligned.m16n8k16.row.col.f32.f16.f16.f32 " \
                 "{%0,%1,%2,%3}, {%4,%5,%6,%7}, {%8,%9}, {%0,%1,%2,%3};" \
                 : "+f"(c0), "+f"(c1), "+f"(c2), "+f"(c3) \
                 : "r"(a0), "r"(a1), "r"(a2), "r"(a3), "r"(b0), "r"(b1))

// ---------------------------------------------------------------------------
// Kernel 1 (merged): blocks [0, 8192) = LN+quant rows; [8192, 24576) = wconv
// ---------------------------------------------------------------------------
__global__ void __launch_bounds__(256) prep_kernel(
    const float* __restrict__ x, const float* __restrict__ w,
    const float* __restrict__ lng, const float* __restrict__ lnb,
    const float* __restrict__ bet, const float* __restrict__ gam)
{
    int tid = threadIdx.x;
    if (blockIdx.x < 8192) {
        int row = blockIdx.x;
        const float4* xr = reinterpret_cast<const float4*>(x + (size_t)row * K_TOT);

        float4 v[4];
        float s = 0.f, s2 = 0.f;
#pragma unroll
        for (int i = 0; i < 4; i++) {
            v[i] = xr[tid + i * 256];
            s  += v[i].x + v[i].y + v[i].z + v[i].w;
            s2 += v[i].x * v[i].x + v[i].y * v[i].y + v[i].z * v[i].z + v[i].w * v[i].w;
        }
#pragma unroll
        for (int o = 16; o; o >>= 1) {
            s  += __shfl_xor_sync(0xffffffffu, s, o);
            s2 += __shfl_xor_sync(0xffffffffu, s2, o);
        }
        __shared__ float rs[8], rs2[8];
        if ((tid & 31) == 0) { rs[tid >> 5] = s; rs2[tid >> 5] = s2; }
        __syncthreads();
        s = 0.f; s2 = 0.f;
#pragma unroll
        for (int i = 0; i < 8; i++) { s += rs[i]; s2 += rs2[i]; }

        const float inv_k = 1.0f / (float)K_TOT;
        float mu   = s * inv_k;
        float var  = s2 * inv_k - mu * mu;
        float rstd = rsqrtf(var + 1e-5f);
        float g  = *gam;
        float qs = 128.0f / g;
        float os = (*bet) * g * (1.0f / 128.0f);
        const float lo = -128.0f + 0.01f;
        const float hi =  128.0f - 0.01f;

        const float4* lg4 = reinterpret_cast<const float4*>(lng);
        const float4* lb4 = reinterpret_cast<const float4*>(lnb);
        uint2* dst = reinterpret_cast<uint2*>(g_A + (size_t)row * K_TOT);

#pragma unroll
        for (int i = 0; i < 4; i++) {
            int idx = tid + i * 256;
            float4 gv = lg4[idx], bv = lb4[idx];
            float e0 = ((v[i].x - mu) * rstd * gv.x + bv.x) * qs;
            float e1 = ((v[i].y - mu) * rstd * gv.y + bv.y) * qs;
            float e2 = ((v[i].z - mu) * rstd * gv.z + bv.z) * qs;
            float e3 = ((v[i].w - mu) * rstd * gv.w + bv.w) * qs;
            e0 = fminf(fmaxf(e0, lo), hi) * os;
            e1 = fminf(fmaxf(e1, lo), hi) * os;
            e2 = fminf(fmaxf(e2, lo), hi) * os;
            e3 = fminf(fmaxf(e3, lo), hi) * os;
            __half2 h0 = __floats2half2_rn(e0, e1);
            __half2 h1 = __floats2half2_rn(e2, e3);
            uint2 u;
            u.x = *reinterpret_cast<uint32_t*>(&h0);
            u.y = *reinterpret_cast<uint32_t*>(&h1);
            dst[idx] = u;
        }
    } else {
        __shared__ float t[32][33];
        int b2 = blockIdx.x - 8192;
        int k0 = (b2 & 127) * 32, n0 = (b2 >> 7) * 32;
        int tx = tid & 31, ty = tid >> 5;
#pragma unroll
        for (int j = 0; j < 32; j += 8)
            t[ty + j][tx] = w[(size_t)(k0 + ty + j) * N_TOT + n0 + tx];
        __syncthreads();
#pragma unroll
        for (int pass = 0; pass < 2; pass++) {
            int idx = tid + pass * 256;
            int n  = idx >> 4;
            int kp = idx & 15;
            __half2 h = __floats2half2_rn(t[2 * kp][n], t[2 * kp + 1][n]);
            *reinterpret_cast<__half2*>(&g_Bt[(size_t)(n0 + n) * K_TOT + k0 + 2 * kp]) = h;
        }
    }
}

// ---------------------------------------------------------------------------
// Kernel 2: HMMA GEMM  out[M,N] = A[M,K] @ Bt[N,K]^T
//   CTA 128x256, BK=64, 4 stages, 512 threads / 16 warps (4m x 4n) of 32x64.
//   SMEM rows 144 B -> conflict-free ldmatrix. Cross-kt fragment prefetch.
// ---------------------------------------------------------------------------
constexpr int BM = 128, BN = 256, BK = 64, STAGES = 4;
constexpr int KT = K_TOT / BK;                     // 64
constexpr int ROW_B = 144;                         // padded row bytes
constexpr int A_STAGE = BM * ROW_B;                // 18432
constexpr int B_STAGE = BN * ROW_B;                // 36864
constexpr int STAGE_B = A_STAGE + B_STAGE;         // 55296
constexpr int SMEM_GEMM = STAGES * STAGE_B;        // 221184
constexpr int NT = 512;

__global__ void __launch_bounds__(NT, 1) gemm_kernel(float* __restrict__ out)
{
    extern __shared__ char smem[];
    uint32_t sb = smem_u32(smem);
    int tid = threadIdx.x;
    int wid = tid >> 5;
    int lid = tid & 31;
    int n0 = blockIdx.x * BN;
    int m0 = blockIdx.y * BM;

    int wm = wid & 3;              // m offset wm*32
    int wn = wid >> 2;             // n offset wn*64

    const __half* gA = g_A + (size_t)m0 * K_TOT;
    const __half* gB = g_Bt + (size_t)n0 * K_TOT;

    // per-lane ldmatrix base offsets (within a stage)
    uint32_t a_off = (uint32_t)(wm * 32 + (lid & 15)) * ROW_B + (uint32_t)(lid >> 4) * 16;
    uint32_t b_off = (uint32_t)(wn * 64 + (lid & 7) + ((lid & 16) ? 8 : 0)) * ROW_B
                   + (uint32_t)((lid & 8) ? 16 : 0);

    float acc[2][8][4];
#pragma unroll
    for (int i = 0; i < 2; i++)
#pragma unroll
        for (int j = 0; j < 8; j++)
#pragma unroll
            for (int q = 0; q < 4; q++) acc[i][j][q] = 0.f;

    // A: 1024 16B chunks (2/thread), B: 2048 (4/thread); row = idx>>3, ch = idx&7
#define LOAD_STAGE(stg, kofs)                                                        \
    do {                                                                             \
        uint32_t _st = sb + (uint32_t)(stg) * STAGE_B;                               \
        _Pragma("unroll")                                                            \
        for (int r = 0; r < 2; r++) {                                                \
            int idx = tid + r * NT;                                                  \
            CP_ASYNC16(_st + (uint32_t)(idx >> 3) * ROW_B + (uint32_t)(idx & 7) * 16,\
                       gA + (size_t)(idx >> 3) * K_TOT + (kofs) + (idx & 7) * 8);    \
        }                                                                            \
        _Pragma("unroll")                                                            \
        for (int r = 0; r < 4; r++) {                                                \
            int idx = tid + r * NT;                                                  \
            CP_ASYNC16(_st + A_STAGE + (uint32_t)(idx >> 3) * ROW_B                  \
                           + (uint32_t)(idx & 7) * 16,                               \
                       gB + (size_t)(idx >> 3) * K_TOT + (kofs) + (idx & 7) * 8);    \
        }                                                                            \
        CP_COMMIT();                                                                 \
    } while (0)

#define LOAD_FRAGS(buf, sa, sB, kh)                                                  \
    do {                                                                             \
        _Pragma("unroll")                                                            \
        for (int mt = 0; mt < 2; mt++)                                               \
            LDSM_X4(af[buf][mt][0], af[buf][mt][1], af[buf][mt][2], af[buf][mt][3],  \
                    (sa) + (uint32_t)mt * (16 * ROW_B) + (uint32_t)(kh) * 32);       \
        _Pragma("unroll")                                                            \
        for (int nb = 0; nb < 4; nb++)                                               \
            LDSM_X4(bf[buf][nb][0], bf[buf][nb][1], bf[buf][nb][2], bf[buf][nb][3],  \
                    (sB) + (uint32_t)nb * (16 * ROW_B) + (uint32_t)(kh) * 32);       \
    } while (0)

    // prologue: fill stages 0..2
#pragma unroll
    for (int s = 0; s < STAGES - 1; s++) LOAD_STAGE(s, s * BK);

    uint32_t af[2][2][4], bf[2][4][4];

    // preload frags for kt=0, kh=0 (stage 0 guaranteed by WAIT(2)+sync)
    CP_WAIT(2);
    __syncthreads();
    LOAD_FRAGS(0, sb + a_off, sb + A_STAGE + b_off, 0);

    int s_load = STAGES - 1;

    for (int kt = 0; kt < KT; kt++) {
        // stages kt AND kt+1 guaranteed resident after this wait
        CP_WAIT(1);
        __syncthreads();

        if (kt + STAGES - 1 < KT) {
            LOAD_STAGE(s_load, (kt + STAGES - 1) * BK);
        } else {
            CP_COMMIT();   // keep group ledger aligned with CP_WAIT(1)
        }
        if (++s_load == STAGES) s_load = 0;

        uint32_t sa_cur = sb + (uint32_t)(kt & 3) * STAGE_B + a_off;
        uint32_t sB_cur = sb + (uint32_t)(kt & 3) * STAGE_B + A_STAGE + b_off;
        uint32_t sa_nxt = sb + (uint32_t)((kt + 1) & 3) * STAGE_B + a_off;
        uint32_t sB_nxt = sb + (uint32_t)((kt + 1) & 3) * STAGE_B + A_STAGE + b_off;

#pragma unroll
        for (int kh = 0; kh < 4; kh++) {
            int cur = kh & 1;
            if (kh < 3) {
                LOAD_FRAGS(cur ^ 1, sa_cur, sB_cur, kh + 1);
            } else {
                LOAD_FRAGS(cur ^ 1, sa_nxt, sB_nxt, 0);  // next kt, kh0
            }
#pragma unroll
            for (int mt = 0; mt < 2; mt++) {
#pragma unroll
                for (int nb = 0; nb < 4; nb++) {
                    MMA16816(acc[mt][2 * nb][0], acc[mt][2 * nb][1],
                             acc[mt][2 * nb][2], acc[mt][2 * nb][3],
                             af[cur][mt][0], af[cur][mt][1], af[cur][mt][2], af[cur][mt][3],
                             bf[cur][nb][0], bf[cur][nb][1]);
                    MMA16816(acc[mt][2 * nb + 1][0], acc[mt][2 * nb + 1][1],
                             acc[mt][2 * nb + 1][2], acc[mt][2 * nb + 1][3],
                             af[cur][mt][0], af[cur][mt][1], af[cur][mt][2], af[cur][mt][3],
                             bf[cur][nb][2], bf[cur][nb][3]);
                }
            }
        }
    }

    // epilogue: direct v2 stores
    int r_base = m0 + wm * 32 + (lid >> 2);
    int c_base = n0 + wn * 64 + 2 * (lid & 3);
#pragma unroll
    for (int mt = 0; mt < 2; mt++) {
#pragma unroll
        for (int nt = 0; nt < 8; nt++) {
            int r = r_base + mt * 16;
            int c = c_base + nt * 8;
            float* p0 = out + (size_t)r * N_TOT + c;
            float* p1 = out + (size_t)(r + 8) * N_TOT + c;
            p0[0] = acc[mt][nt][0]; p0[1] = acc[mt][nt][1];
            p1[0] = acc[mt][nt][2]; p1[1] = acc[mt][nt][3];
        }
    }
}

// ---------------------------------------------------------------------------
extern "C" void kernel_launch(void* const* d_in, const int* in_sizes, int n_in,
                              void* d_out, int out_size)
{
    const float* x     = (const float*)d_in[0];
    const float* w     = (const float*)d_in[1];
    const float* lng   = (const float*)d_in[2];
    const float* lnb   = (const float*)d_in[3];
    const float* beta  = (const float*)d_in[4];
    const float* gamma = (const float*)d_in[5];
    float* out = (float*)d_out;

    prep_kernel<<<8192 + 16384, 256>>>(x, w, lng, lnb, beta, gamma);

    cudaFuncSetAttribute(gemm_kernel,
                         cudaFuncAttributeMaxDynamicSharedMemorySize, SMEM_GEMM);
    gemm_kernel<<<dim3(N_TOT / BN, M_TOT / BM), NT, SMEM_GEMM>>>(out);
}

// round 16
// speedup vs baseline: 1.1441x; 1.0050x over previous
#include <cuda_runtime.h>
#include <cuda_fp16.h>
#include <cstdint>

// ============================================================================
// BitLinear: y = (clip(LN(x) * 128/gamma, +-(128-.01)) @ w) * beta*gamma/128
//   x: [4,2048,4096] f32 -> M=8192, K=4096;  w: [4096,4096] f32 (+-1)
// Base sm_100 target (no tcgen05). mma.sync HMMA + ldmatrix + cp.async.
// R16: GEMM frozen byte-identical to R6/R15 (787 us, at the mma.sync issue
// ceiling). Prep micro-opts only: lnq loads staged via cp.async (no dest-reg
// pressure, deeper MLP); wconv 64x64 tiles with float4 loads and full-line
// (128 B) coalesced Bt writes.
// ============================================================================

constexpr int M_TOT = 8192;
constexpr int N_TOT = 4096;
constexpr int K_TOT = 4096;

__device__ __half g_A[(size_t)M_TOT * K_TOT];   // 64 MB
__device__ __half g_Bt[(size_t)N_TOT * K_TOT];  // 32 MB

// ---------------------------------------------------------------------------
__device__ __forceinline__ uint32_t smem_u32(const void* p) {
    uint32_t a;
    asm("{ .reg .u64 t; cvta.to.shared.u64 t, %1; cvt.u32.u64 %0, t; }"
        : "=r"(a) : "l"(p));
    return a;
}

#define CP_ASYNC16(smem, gptr) \
    asm volatile("cp.async.cg.shared.global [%0], [%1], 16;" \
                 :: "r"(smem), "l"(gptr) : "memory")
#define CP_COMMIT() asm volatile("cp.async.commit_group;" ::: "memory")
#define CP_WAIT(n)  asm volatile("cp.async.wait_group %0;" :: "n"(n) : "memory")

#define LDSM_X4(r0, r1, r2, r3, addr) \
    asm volatile("ldmatrix.sync.aligned.m8n8.x4.shared.b16 {%0,%1,%2,%3}, [%4];" \
                 : "=r"(r0), "=r"(r1), "=r"(r2), "=r"(r3) : "r"(addr))

#define MMA16816(c0, c1, c2, c3, a0, a1, a2, a3, b0, b1) \
    asm volatile("mma.sync.aligned.m16n8k16.row.col.f32.f16.f16.f32 " \
                 "{%0,%1,%2,%3}, {%4,%5,%6,%7}, {%8,%9}, {%0,%1,%2,%3};" \
                 : "+f"(c0), "+f"(c1), "+f"(c2), "+f"(c3) \
                 : "r"(a0), "r"(a1), "r"(a2), "r"(a3), "r"(b0), "r"(b1))

// ---------------------------------------------------------------------------
// Kernel 1 (merged): blocks [0, 8192) = LN+quant rows (cp.async staged);
// blocks [8192, 12288) = wconv 64x64 transpose (full-line writes).
// ---------------------------------------------------------------------------
__global__ void __launch_bounds__(256) prep_kernel(
    const float* __restrict__ x, const float* __restrict__ w,
    const float* __restrict__ lng, const float* __restrict__ lnb,
    const float* __restrict__ bet, const float* __restrict__ gam)
{
    __shared__ float sbuf[4480];   // 17.9 KB, shared by both branches
    int tid = threadIdx.x;

    if (blockIdx.x < 8192) {
        // ---- LayerNorm + quant + clip + scale-fold -> g_A (fp16) ----
        int row = blockIdx.x;
        float* xs  = sbuf;          // 4096 floats: the row
        float* rs  = sbuf + 4096;   // 8 warp partials
        float* rs2 = sbuf + 4104;   // 8 warp partials
        uint32_t sx = smem_u32(xs);
        const float* xr = x + (size_t)row * K_TOT;

        // stage the whole row via cp.async (no dest-register pressure)
#pragma unroll
        for (int i = 0; i < 4; i++) {
            int idx = tid + i * 256;
            CP_ASYNC16(sx + (uint32_t)idx * 16, xr + idx * 4);
        }
        CP_COMMIT();
        CP_WAIT(0);
        __syncthreads();

        const float4* xs4 = reinterpret_cast<const float4*>(xs);
        float4 v[4];
        float s = 0.f, s2 = 0.f;
#pragma unroll
        for (int i = 0; i < 4; i++) {
            v[i] = xs4[tid + i * 256];
            s  += v[i].x + v[i].y + v[i].z + v[i].w;
            s2 += v[i].x * v[i].x + v[i].y * v[i].y + v[i].z * v[i].z + v[i].w * v[i].w;
        }
#pragma unroll
        for (int o = 16; o; o >>= 1) {
            s  += __shfl_xor_sync(0xffffffffu, s, o);
            s2 += __shfl_xor_sync(0xffffffffu, s2, o);
        }
        if ((tid & 31) == 0) { rs[tid >> 5] = s; rs2[tid >> 5] = s2; }
        __syncthreads();
        s = 0.f; s2 = 0.f;
#pragma unroll
        for (int i = 0; i < 8; i++) { s += rs[i]; s2 += rs2[i]; }

        const float inv_k = 1.0f / (float)K_TOT;
        float mu   = s * inv_k;
        float var  = s2 * inv_k - mu * mu;
        float rstd = rsqrtf(var + 1e-5f);
        float g  = *gam;
        float qs = 128.0f / g;
        float os = (*bet) * g * (1.0f / 128.0f);
        const float lo = -128.0f + 0.01f;
        const float hi =  128.0f - 0.01f;

        const float4* lg4 = reinterpret_cast<const float4*>(lng);
        const float4* lb4 = reinterpret_cast<const float4*>(lnb);
        uint2* dst = reinterpret_cast<uint2*>(g_A + (size_t)row * K_TOT);

#pragma unroll
        for (int i = 0; i < 4; i++) {
            int idx = tid + i * 256;
            float4 gv = lg4[idx], bv = lb4[idx];
            float e0 = ((v[i].x - mu) * rstd * gv.x + bv.x) * qs;
            float e1 = ((v[i].y - mu) * rstd * gv.y + bv.y) * qs;
            float e2 = ((v[i].z - mu) * rstd * gv.z + bv.z) * qs;
            float e3 = ((v[i].w - mu) * rstd * gv.w + bv.w) * qs;
            e0 = fminf(fmaxf(e0, lo), hi) * os;
            e1 = fminf(fmaxf(e1, lo), hi) * os;
            e2 = fminf(fmaxf(e2, lo), hi) * os;
            e3 = fminf(fmaxf(e3, lo), hi) * os;
            __half2 h0 = __floats2half2_rn(e0, e1);
            __half2 h1 = __floats2half2_rn(e2, e3);
            uint2 u;
            u.x = *reinterpret_cast<uint32_t*>(&h0);
            u.y = *reinterpret_cast<uint32_t*>(&h1);
            dst[idx] = u;
        }
    } else {
        // ---- w[k][n] f32 -> g_Bt[n][k] fp16, 64x64 tile ----
        // t[64][68] floats (padded); load float4, write full 128B lines.
        float* t = sbuf;                        // 64*68 = 4352 floats
        int b2 = blockIdx.x - 8192;
        int k0 = (b2 & 63) * 64, n0 = (b2 >> 6) * 64;

        // load: 1024 float4s, 4/thread. row = idx>>4 (k), c4 = idx&15 (n quad)
        float4* t4 = reinterpret_cast<float4*>(t);
#pragma unroll
        for (int p = 0; p < 4; p++) {
            int idx = tid + p * 256;
            int row = idx >> 4, c4 = idx & 15;
            float4 vv = *reinterpret_cast<const float4*>(
                w + (size_t)(k0 + row) * N_TOT + n0 + c4 * 4);
            t4[row * 17 + c4] = vv;
        }
        __syncthreads();

        // store: 1024 cells (n, k-quad), 4/thread. n = idx>>4, q = idx&15.
        // threads 0..15 share n with consecutive q -> 16 x 8B = 128B lines.
#pragma unroll
        for (int p = 0; p < 4; p++) {
            int idx = tid + p * 256;
            int n = idx >> 4, q = idx & 15;
            float f0 = t[(4 * q + 0) * 68 + n];
            float f1 = t[(4 * q + 1) * 68 + n];
            float f2 = t[(4 * q + 2) * 68 + n];
            float f3 = t[(4 * q + 3) * 68 + n];
            __half2 h0 = __floats2half2_rn(f0, f1);
            __half2 h1 = __floats2half2_rn(f2, f3);
            uint2 u;
            u.x = *reinterpret_cast<uint32_t*>(&h0);
            u.y = *reinterpret_cast<uint32_t*>(&h1);
            *reinterpret_cast<uint2*>(&g_Bt[(size_t)(n0 + n) * K_TOT + k0 + 4 * q]) = u;
        }
    }
}

// ---------------------------------------------------------------------------
// Kernel 2: HMMA GEMM  out[M,N] = A[M,K] @ Bt[N,K]^T   (FROZEN: R6/R15)
//   CTA 128x256, BK=64, 4 stages, 512 threads / 16 warps (4m x 4n) of 32x64.
//   Double-buffered fragments + cross-kt prefetch, CP_WAIT(1).
// ---------------------------------------------------------------------------
constexpr int BM = 128, BN = 256, BK = 64, STAGES = 4;
constexpr int KT = K_TOT / BK;                     // 64
constexpr int ROW_B = 144;                         // padded row bytes
constexpr int A_STAGE = BM * ROW_B;                // 18432
constexpr int B_STAGE = BN * ROW_B;                // 36864
constexpr int STAGE_B = A_STAGE + B_STAGE;         // 55296
constexpr int SMEM_GEMM = STAGES * STAGE_B;        // 221184
constexpr int NT = 512;

__global__ void __launch_bounds__(NT, 1) gemm_kernel(float* __restrict__ out)
{
    extern __shared__ char smem[];
    uint32_t sb = smem_u32(smem);
    int tid = threadIdx.x;
    int wid = tid >> 5;
    int lid = tid & 31;
    int n0 = blockIdx.x * BN;
    int m0 = blockIdx.y * BM;

    int wm = wid & 3;              // m offset wm*32
    int wn = wid >> 2;             // n offset wn*64

    const __half* gA = g_A + (size_t)m0 * K_TOT;
    const __half* gB = g_Bt + (size_t)n0 * K_TOT;

    uint32_t a_off = (uint32_t)(wm * 32 + (lid & 15)) * ROW_B + (uint32_t)(lid >> 4) * 16;
    uint32_t b_off = (uint32_t)(wn * 64 + (lid & 7) + ((lid & 16) ? 8 : 0)) * ROW_B
                   + (uint32_t)((lid & 8) ? 16 : 0);

    float acc[2][8][4];
#pragma unroll
    for (int i = 0; i < 2; i++)
#pragma unroll
        for (int j = 0; j < 8; j++)
#pragma unroll
            for (int q = 0; q < 4; q++) acc[i][j][q] = 0.f;

#define LOAD_STAGE(stg, kofs)                                                        \
    do {                                                                             \
        uint32_t _st = sb + (uint32_t)(stg) * STAGE_B;                               \
        _Pragma("unroll")                                                            \
        for (int r = 0; r < 2; r++) {                                                \
            int idx = tid + r * NT;                                                  \
            CP_ASYNC16(_st + (uint32_t)(idx >> 3) * ROW_B + (uint32_t)(idx & 7) * 16,\
                       gA + (size_t)(idx >> 3) * K_TOT + (kofs) + (idx & 7) * 8);    \
        }                                                                            \
        _Pragma("unroll")                                                            \
        for (int r = 0; r < 4; r++) {                                                \
            int idx = tid + r * NT;                                                  \
            CP_ASYNC16(_st + A_STAGE + (uint32_t)(idx >> 3) * ROW_B                  \
                           + (uint32_t)(idx & 7) * 16,                               \
                       gB + (size_t)(idx >> 3) * K_TOT + (kofs) + (idx & 7) * 8);    \
        }                                                                            \
        CP_COMMIT();                                                                 \
    } while (0)

#define LOAD_FRAGS(buf, sa, sB, kh)                                                  \
    do {                                                                             \
        _Pragma("unroll")                                                            \
        for (int mt = 0; mt < 2; mt++)                                               \
            LDSM_X4(af[buf][mt][0], af[buf][mt][1], af[buf][mt][2], af[buf][mt][3],  \
                    (sa) + (uint32_t)mt * (16 * ROW_B) + (uint32_t)(kh) * 32);       \
        _Pragma("unroll")                                                            \
        for (int nb = 0; nb < 4; nb++)                                               \
            LDSM_X4(bf[buf][nb][0], bf[buf][nb][1], bf[buf][nb][2], bf[buf][nb][3],  \
                    (sB) + (uint32_t)nb * (16 * ROW_B) + (uint32_t)(kh) * 32);       \
    } while (0)

    // prologue: fill stages 0..2
#pragma unroll
    for (int s = 0; s < STAGES - 1; s++) LOAD_STAGE(s, s * BK);

    uint32_t af[2][2][4], bf[2][4][4];

    // preload frags for kt=0, kh=0 (stage 0 guaranteed by WAIT(2)+sync)
    CP_WAIT(2);
    __syncthreads();
    LOAD_FRAGS(0, sb + a_off, sb + A_STAGE + b_off, 0);

    int s_load = STAGES - 1;

    for (int kt = 0; kt < KT; kt++) {
        // stages kt AND kt+1 guaranteed resident after this wait
        CP_WAIT(1);
        __syncthreads();

        if (kt + STAGES - 1 < KT) {
            LOAD_STAGE(s_load, (kt + STAGES - 1) * BK);
        } else {
            CP_COMMIT();   // keep group ledger aligned with CP_WAIT(1)
        }
        if (++s_load == STAGES) s_load = 0;

        uint32_t sa_cur = sb + (uint32_t)(kt & 3) * STAGE_B + a_off;
        uint32_t sB_cur = sb + (uint32_t)(kt & 3) * STAGE_B + A_STAGE + b_off;
        uint32_t sa_nxt = sb + (uint32_t)((kt + 1) & 3) * STAGE_B + a_off;
        uint32_t sB_nxt = sb + (uint32_t)((kt + 1) & 3) * STAGE_B + A_STAGE + b_off;

#pragma unroll
        for (int kh = 0; kh < 4; kh++) {
            int cur = kh & 1;
            if (kh < 3) {
                LOAD_FRAGS(cur ^ 1, sa_cur, sB_cur, kh + 1);
            } else {
                LOAD_FRAGS(cur ^ 1, sa_nxt, sB_nxt, 0);  // next kt, kh0
            }
#pragma unroll
            for (int mt = 0; mt < 2; mt++) {
#pragma unroll
                for (int nb = 0; nb < 4; nb++) {
                    MMA16816(acc[mt][2 * nb][0], acc[mt][2 * nb][1],
                             acc[mt][2 * nb][2], acc[mt][2 * nb][3],
                             af[cur][mt][0], af[cur][mt][1], af[cur][mt][2], af[cur][mt][3],
                             bf[cur][nb][0], bf[cur][nb][1]);
                    MMA16816(acc[mt][2 * nb + 1][0], acc[mt][2 * nb + 1][1],
                             acc[mt][2 * nb + 1][2], acc[mt][2 * nb + 1][3],
                             af[cur][mt][0], af[cur][mt][1], af[cur][mt][2], af[cur][mt][3],
                             bf[cur][nb][2], bf[cur][nb][3]);
                }
            }
        }
    }

    // epilogue: direct v2 stores
    int r_base = m0 + wm * 32 + (lid >> 2);
    int c_base = n0 + wn * 64 + 2 * (lid & 3);
#pragma unroll
    for (int mt = 0; mt < 2; mt++) {
#pragma unroll
        for (int nt = 0; nt < 8; nt++) {
            int r = r_base + mt * 16;
            int c = c_base + nt * 8;
            float* p0 = out + (size_t)r * N_TOT + c;
            float* p1 = out + (size_t)(r + 8) * N_TOT + c;
            p0[0] = acc[mt][nt][0]; p0[1] = acc[mt][nt][1];
            p1[0] = acc[mt][nt][2]; p1[1] = acc[mt][nt][3];
        }
    }
}

// ---------------------------------------------------------------------------
extern "C" void kernel_launch(void* const* d_in, const int* in_sizes, int n_in,
                              void* d_out, int out_size)
{
    const float* x     = (const float*)d_in[0];
    const float* w     = (const float*)d_in[1];
    const float* lng   = (const float*)d_in[2];
    const float* lnb   = (const float*)d_in[3];
    const float* beta  = (const float*)d_in[4];
    const float* gamma = (const float*)d_in[5];
    float* out = (float*)d_out;

    prep_kernel<<<8192 + 4096, 256>>>(x, w, lng, lnb, beta, gamma);

    cudaFuncSetAttribute(gemm_kernel,
                         cudaFuncAttributeMaxDynamicSharedMemorySize, SMEM_GEMM);
    gemm_kernel<<<dim3(N_TOT / BN, M_TOT / BM), NT, SMEM_GEMM>>>(out);
}

// round 17
// speedup vs baseline: 1.1460x; 1.0017x over previous
#include <cuda_runtime.h>
#include <cuda_fp16.h>
#include <cstdint>

// ============================================================================
// BitLinear: y = (clip(LN(x) * 128/gamma, +-(128-.01)) @ w) * beta*gamma/128
//   x: [4,2048,4096] f32 -> M=8192, K=4096;  w: [4096,4096] f32 (+-1)
// Base sm_100 target (no tcgen05). mma.sync HMMA + ldmatrix + cp.async.
// R16: GEMM frozen byte-identical to R6/R15 (787 us, at the mma.sync issue
// ceiling). Prep micro-opts only: lnq loads staged via cp.async (no dest-reg
// pressure, deeper MLP); wconv 64x64 tiles with float4 loads and full-line
// (128 B) coalesced Bt writes.
// ============================================================================

constexpr int M_TOT = 8192;
constexpr int N_TOT = 4096;
constexpr int K_TOT = 4096;

__device__ __half g_A[(size_t)M_TOT * K_TOT];   // 64 MB
__device__ __half g_Bt[(size_t)N_TOT * K_TOT];  // 32 MB

// ---------------------------------------------------------------------------
__device__ __forceinline__ uint32_t smem_u32(const void* p) {
    uint32_t a;
    asm("{ .reg .u64 t; cvta.to.shared.u64 t, %1; cvt.u32.u64 %0, t; }"
        : "=r"(a) : "l"(p));
    return a;
}

#define CP_ASYNC16(smem, gptr) \
    asm volatile("cp.async.cg.shared.global [%0], [%1], 16;" \
                 :: "r"(smem), "l"(gptr) : "memory")
#define CP_COMMIT() asm volatile("cp.async.commit_group;" ::: "memory")
#define CP_WAIT(n)  asm volatile("cp.async.wait_group %0;" :: "n"(n) : "memory")

#define LDSM_X4(r0, r1, r2, r3, addr) \
    asm volatile("ldmatrix.sync.aligned.m8n8.x4.shared.b16 {%0,%1,%2,%3}, [%4];" \
                 : "=r"(r0), "=r"(r1), "=r"(r2), "=r"(r3) : "r"(addr))

#define MMA16816(c0, c1, c2, c3, a0, a1, a2, a3, b0, b1) \
    asm volatile("mma.sync.aligned.m16n8k16.row.col.f32.f16.f16.f32 " \
                 "{%0,%1,%2,%3}, {%4,%5,%6,%7}, {%8,%9}, {%0,%1,%2,%3};" \
                 : "+f"(c0), "+f"(c1), "+f"(c2), "+f"(c3) \
                 : "r"(a0), "r"(a1), "r"(a2), "r"(a3), "r"(b0), "r"(b1))

// ---------------------------------------------------------------------------
// Kernel 1 (merged): blocks [0, 8192) = LN+quant rows (cp.async staged);
// blocks [8192, 12288) = wconv 64x64 transpose (full-line writes).
// ---------------------------------------------------------------------------
__global__ void __launch_bounds__(256) prep_kernel(
    const float* __restrict__ x, const float* __restrict__ w,
    const float* __restrict__ lng, const float* __restrict__ lnb,
    const float* __restrict__ bet, const float* __restrict__ gam)
{
    __shared__ float sbuf[4480];   // 17.9 KB, shared by both branches
    int tid = threadIdx.x;

    if (blockIdx.x < 8192) {
        // ---- LayerNorm + quant + clip + scale-fold -> g_A (fp16) ----
        int row = blockIdx.x;
        float* xs  = sbuf;          // 4096 floats: the row
        float* rs  = sbuf + 4096;   // 8 warp partials
        float* rs2 = sbuf + 4104;   // 8 warp partials
        uint32_t sx = smem_u32(xs);
        const float* xr = x + (size_t)row * K_TOT;

        // stage the whole row via cp.async (no dest-register pressure)
#pragma unroll
        for (int i = 0; i < 4; i++) {
            int idx = tid + i * 256;
            CP_ASYNC16(sx + (uint32_t)idx * 16, xr + idx * 4);
        }
        CP_COMMIT();
        CP_WAIT(0);
        __syncthreads();

        const float4* xs4 = reinterpret_cast<const float4*>(xs);
        float4 v[4];
        float s = 0.f, s2 = 0.f;
#pragma unroll
        for (int i = 0; i < 4; i++) {
            v[i] = xs4[tid + i * 256];
            s  += v[i].x + v[i].y + v[i].z + v[i].w;
            s2 += v[i].x * v[i].x + v[i].y * v[i].y + v[i].z * v[i].z + v[i].w * v[i].w;
        }
#pragma unroll
        for (int o = 16; o; o >>= 1) {
            s  += __shfl_xor_sync(0xffffffffu, s, o);
            s2 += __shfl_xor_sync(0xffffffffu, s2, o);
        }
        if ((tid & 31) == 0) { rs[tid >> 5] = s; rs2[tid >> 5] = s2; }
        __syncthreads();
        s = 0.f; s2 = 0.f;
#pragma unroll
        for (int i = 0; i < 8; i++) { s += rs[i]; s2 += rs2[i]; }

        const float inv_k = 1.0f / (float)K_TOT;
        float mu   = s * inv_k;
        float var  = s2 * inv_k - mu * mu;
        float rstd = rsqrtf(var + 1e-5f);
        float g  = *gam;
        float qs = 128.0f / g;
        float os = (*bet) * g * (1.0f / 128.0f);
        const float lo = -128.0f + 0.01f;
        const float hi =  128.0f - 0.01f;

        const float4* lg4 = reinterpret_cast<const float4*>(lng);
        const float4* lb4 = reinterpret_cast<const float4*>(lnb);
        uint2* dst = reinterpret_cast<uint2*>(g_A + (size_t)row * K_TOT);

#pragma unroll
        for (int i = 0; i < 4; i++) {
            int idx = tid + i * 256;
            float4 gv = lg4[idx], bv = lb4[idx];
            float e0 = ((v[i].x - mu) * rstd * gv.x + bv.x) * qs;
            float e1 = ((v[i].y - mu) * rstd * gv.y + bv.y) * qs;
            float e2 = ((v[i].z - mu) * rstd * gv.z + bv.z) * qs;
            float e3 = ((v[i].w - mu) * rstd * gv.w + bv.w) * qs;
            e0 = fminf(fmaxf(e0, lo), hi) * os;
            e1 = fminf(fmaxf(e1, lo), hi) * os;
            e2 = fminf(fmaxf(e2, lo), hi) * os;
            e3 = fminf(fmaxf(e3, lo), hi) * os;
            __half2 h0 = __floats2half2_rn(e0, e1);
            __half2 h1 = __floats2half2_rn(e2, e3);
            uint2 u;
            u.x = *reinterpret_cast<uint32_t*>(&h0);
            u.y = *reinterpret_cast<uint32_t*>(&h1);
            dst[idx] = u;
        }
    } else {
        // ---- w[k][n] f32 -> g_Bt[n][k] fp16, 64x64 tile ----
        // t[64][68] floats (padded); load float4, write full 128B lines.
        float* t = sbuf;                        // 64*68 = 4352 floats
        int b2 = blockIdx.x - 8192;
        int k0 = (b2 & 63) * 64, n0 = (b2 >> 6) * 64;

        // load: 1024 float4s, 4/thread. row = idx>>4 (k), c4 = idx&15 (n quad)
        float4* t4 = reinterpret_cast<float4*>(t);
#pragma unroll
        for (int p = 0; p < 4; p++) {
            int idx = tid + p * 256;
            int row = idx >> 4, c4 = idx & 15;
            float4 vv = *reinterpret_cast<const float4*>(
                w + (size_t)(k0 + row) * N_TOT + n0 + c4 * 4);
            t4[row * 17 + c4] = vv;
        }
        __syncthreads();

        // store: 1024 cells (n, k-quad), 4/thread. n = idx>>4, q = idx&15.
        // threads 0..15 share n with consecutive q -> 16 x 8B = 128B lines.
#pragma unroll
        for (int p = 0; p < 4; p++) {
            int idx = tid + p * 256;
            int n = idx >> 4, q = idx & 15;
            float f0 = t[(4 * q + 0) * 68 + n];
            float f1 = t[(4 * q + 1) * 68 + n];
            float f2 = t[(4 * q + 2) * 68 + n];
            float f3 = t[(4 * q + 3) * 68 + n];
            __half2 h0 = __floats2half2_rn(f0, f1);
            __half2 h1 = __floats2half2_rn(f2, f3);
            uint2 u;
            u.x = *reinterpret_cast<uint32_t*>(&h0);
            u.y = *reinterpret_cast<uint32_t*>(&h1);
            *reinterpret_cast<uint2*>(&g_Bt[(size_t)(n0 + n) * K_TOT + k0 + 4 * q]) = u;
        }
    }
}

// ---------------------------------------------------------------------------
// Kernel 2: HMMA GEMM  out[M,N] = A[M,K] @ Bt[N,K]^T   (FROZEN: R6/R15)
//   CTA 128x256, BK=64, 4 stages, 512 threads / 16 warps (4m x 4n) of 32x64.
//   Double-buffered fragments + cross-kt prefetch, CP_WAIT(1).
// ---------------------------------------------------------------------------
constexpr int BM = 128, BN = 256, BK = 64, STAGES = 4;
constexpr int KT = K_TOT / BK;                     // 64
constexpr int ROW_B = 144;                         // padded row bytes
constexpr int A_STAGE = BM * ROW_B;                // 18432
constexpr int B_STAGE = BN * ROW_B;                // 36864
constexpr int STAGE_B = A_STAGE + B_STAGE;         // 55296
constexpr int SMEM_GEMM = STAGES * STAGE_B;        // 221184
constexpr int NT = 512;

__global__ void __launch_bounds__(NT, 1) gemm_kernel(float* __restrict__ out)
{
    extern __shared__ char smem[];
    uint32_t sb = smem_u32(smem);
    int tid = threadIdx.x;
    int wid = tid >> 5;
    int lid = tid & 31;
    int n0 = blockIdx.x * BN;
    int m0 = blockIdx.y * BM;

    int wm = wid & 3;              // m offset wm*32
    int wn = wid >> 2;             // n offset wn*64

    const __half* gA = g_A + (size_t)m0 * K_TOT;
    const __half* gB = g_Bt + (size_t)n0 * K_TOT;

    uint32_t a_off = (uint32_t)(wm * 32 + (lid & 15)) * ROW_B + (uint32_t)(lid >> 4) * 16;
    uint32_t b_off = (uint32_t)(wn * 64 + (lid & 7) + ((lid & 16) ? 8 : 0)) * ROW_B
                   + (uint32_t)((lid & 8) ? 16 : 0);

    float acc[2][8][4];
#pragma unroll
    for (int i = 0; i < 2; i++)
#pragma unroll
        for (int j = 0; j < 8; j++)
#pragma unroll
            for (int q = 0; q < 4; q++) acc[i][j][q] = 0.f;

#define LOAD_STAGE(stg, kofs)                                                        \
    do {                                                                             \
        uint32_t _st = sb + (uint32_t)(stg) * STAGE_B;                               \
        _Pragma("unroll")                                                            \
        for (int r = 0; r < 2; r++) {                                                \
            int idx = tid + r * NT;                                                  \
            CP_ASYNC16(_st + (uint32_t)(idx >> 3) * ROW_B + (uint32_t)(idx & 7) * 16,\
                       gA + (size_t)(idx >> 3) * K_TOT + (kofs) + (idx & 7) * 8);    \
        }                                                                            \
        _Pragma("unroll")                                                            \
        for (int r = 0; r < 4; r++) {                                                \
            int idx = tid + r * NT;                                                  \
            CP_ASYNC16(_st + A_STAGE + (uint32_t)(idx >> 3) * ROW_B                  \
                           + (uint32_t)(idx & 7) * 16,                               \
                       gB + (size_t)(idx >> 3) * K_TOT + (kofs) + (idx & 7) * 8);    \
        }                                                                            \
        CP_COMMIT();                                                                 \
    } while (0)

#define LOAD_FRAGS(buf, sa, sB, kh)                                                  \
    do {                                                                             \
        _Pragma("unroll")                                                            \
        for (int mt = 0; mt < 2; mt++)                                               \
            LDSM_X4(af[buf][mt][0], af[buf][mt][1], af[buf][mt][2], af[buf][mt][3],  \
                    (sa) + (uint32_t)mt * (16 * ROW_B) + (uint32_t)(kh) * 32);       \
        _Pragma("unroll")                                                            \
        for (int nb = 0; nb < 4; nb++)                                               \
            LDSM_X4(bf[buf][nb][0], bf[buf][nb][1], bf[buf][nb][2], bf[buf][nb][3],  \
                    (sB) + (uint32_t)nb * (16 * ROW_B) + (uint32_t)(kh) * 32);       \
    } while (0)

    // prologue: fill stages 0..2
#pragma unroll
    for (int s = 0; s < STAGES - 1; s++) LOAD_STAGE(s, s * BK);

    uint32_t af[2][2][4], bf[2][4][4];

    // preload frags for kt=0, kh=0 (stage 0 guaranteed by WAIT(2)+sync)
    CP_WAIT(2);
    __syncthreads();
    LOAD_FRAGS(0, sb + a_off, sb + A_STAGE + b_off, 0);

    int s_load = STAGES - 1;

    for (int kt = 0; kt < KT; kt++) {
        // stages kt AND kt+1 guaranteed resident after this wait
        CP_WAIT(1);
        __syncthreads();

        if (kt + STAGES - 1 < KT) {
            LOAD_STAGE(s_load, (kt + STAGES - 1) * BK);
        } else {
            CP_COMMIT();   // keep group ledger aligned with CP_WAIT(1)
        }
        if (++s_load == STAGES) s_load = 0;

        uint32_t sa_cur = sb + (uint32_t)(kt & 3) * STAGE_B + a_off;
        uint32_t sB_cur = sb + (uint32_t)(kt & 3) * STAGE_B + A_STAGE + b_off;
        uint32_t sa_nxt = sb + (uint32_t)((kt + 1) & 3) * STAGE_B + a_off;
        uint32_t sB_nxt = sb + (uint32_t)((kt + 1) & 3) * STAGE_B + A_STAGE + b_off;

#pragma unroll
        for (int kh = 0; kh < 4; kh++) {
            int cur = kh & 1;
            if (kh < 3) {
                LOAD_FRAGS(cur ^ 1, sa_cur, sB_cur, kh + 1);
            } else {
                LOAD_FRAGS(cur ^ 1, sa_nxt, sB_nxt, 0);  // next kt, kh0
            }
#pragma unroll
            for (int mt = 0; mt < 2; mt++) {
#pragma unroll
                for (int nb = 0; nb < 4; nb++) {
                    MMA16816(acc[mt][2 * nb][0], acc[mt][2 * nb][1],
                             acc[mt][2 * nb][2], acc[mt][2 * nb][3],
                             af[cur][mt][0], af[cur][mt][1], af[cur][mt][2], af[cur][mt][3],
                             bf[cur][nb][0], bf[cur][nb][1]);
                    MMA16816(acc[mt][2 * nb + 1][0], acc[mt][2 * nb + 1][1],
                             acc[mt][2 * nb + 1][2], acc[mt][2 * nb + 1][3],
                             af[cur][mt][0], af[cur][mt][1], af[cur][mt][2], af[cur][mt][3],
                             bf[cur][nb][2], bf[cur][nb][3]);
                }
            }
        }
    }

    // epilogue: direct v2 stores
    int r_base = m0 + wm * 32 + (lid >> 2);
    int c_base = n0 + wn * 64 + 2 * (lid & 3);
#pragma unroll
    for (int mt = 0; mt < 2; mt++) {
#pragma unroll
        for (int nt = 0; nt < 8; nt++) {
            int r = r_base + mt * 16;
            int c = c_base + nt * 8;
            float* p0 = out + (size_t)r * N_TOT + c;
            float* p1 = out + (size_t)(r + 8) * N_TOT + c;
            p0[0] = acc[mt][nt][0]; p0[1] = acc[mt][nt][1];
            p1[0] = acc[mt][nt][2]; p1[1] = acc[mt][nt][3];
        }
    }
}

// ---------------------------------------------------------------------------
extern "C" void kernel_launch(void* const* d_in, const int* in_sizes, int n_in,
                              void* d_out, int out_size)
{
    const float* x     = (const float*)d_in[0];
    const float* w     = (const float*)d_in[1];
    const float* lng   = (const float*)d_in[2];
    const float* lnb   = (const float*)d_in[3];
    const float* beta  = (const float*)d_in[4];
    const float* gamma = (const float*)d_in[5];
    float* out = (float*)d_out;

    prep_kernel<<<8192 + 4096, 256>>>(x, w, lng, lnb, beta, gamma);

    cudaFuncSetAttribute(gemm_kernel,
                         cudaFuncAttributeMaxDynamicSharedMemorySize, SMEM_GEMM);
    gemm_kernel<<<dim3(N_TOT / BN, M_TOT / BM), NT, SMEM_GEMM>>>(out);
}